// round 13
// baseline (speedup 1.0000x reference)
#include <cuda_runtime.h>
#include <cuda_bf16.h>
#include <cuda_fp16.h>
#include <cub/cub.cuh>
#include <cstdint>

#define ALPHA_F 10.0f
#define DELTA_F 0.0005f
#define ITEMS 8
#define SEED_OFF 8389          // delta * N for N=2^24; verified at runtime, fallback-safe
#define SEED_HALF 1024

// ---- scratch (device globals: allocation-free rule) ----
__device__ float        g_clamped[16777216];
__device__ float        g_xs[16777216];
__device__ unsigned int g_idx_in[16777216];
__device__ unsigned int g_idx[16777216];
__device__ float        g_ys[16777216];
__device__ __half2      g_AB[16777216];                 // 64 MB: fits L2 -> scatter stays on-chip
__device__ unsigned char g_temp[200u * 1024u * 1024u];
__device__ double       g_accum;

__global__ __launch_bounds__(256) void k_init(const float4* __restrict__ in4, int n4) {
    int t = blockIdx.x * blockDim.x + threadIdx.x;
    if (t == 0) g_accum = 0.0;
    if (t >= n4) return;
    float4 v = __ldg(&in4[t]);
    float4 c;
    c.x = fminf(fmaxf(v.x, 0.0f), 1.0f);
    c.y = fminf(fmaxf(v.y, 0.0f), 1.0f);
    c.z = fminf(fmaxf(v.z, 0.0f), 1.0f);
    c.w = fminf(fmaxf(v.w, 0.0f), 1.0f);
    ((float4*)g_clamped)[t] = c;
    unsigned int i0 = (unsigned int)t * 4u;
    ((uint4*)g_idx_in)[t] = make_uint4(i0, i0 + 1, i0 + 2, i0 + 3);
}

__global__ __launch_bounds__(256) void k_gather(const float* __restrict__ array, int n4) {
    int t = blockIdx.x * blockDim.x + threadIdx.x;
    if (t >= n4) return;
    uint4 id = __ldg(&((const uint4*)g_idx)[t]);
    float4 y;
    y.x = __ldg(&array[id.x]);
    y.y = __ldg(&array[id.y]);
    y.z = __ldg(&array[id.z]);
    y.w = __ldg(&array[id.w]);
    ((float4*)g_ys)[t] = y;
}

// first index in [lo,hi) with xs > q
__device__ __forceinline__ int bsearch_gt(float q, int lo, int hi) {
    while (lo < hi) {
        int mid = (lo + hi) >> 1;
        if (__ldg(&g_xs[mid]) <= q) lo = mid + 1; else hi = mid;
    }
    return lo;
}

// Each thread owns ITEMS consecutive sorted positions; bracket indices are
// monotone in k. One seeded/galloped search per side, then linear advance.
// np.interp semantics: j = last index with xs[j] <= q.
__global__ __launch_bounds__(256) void k_interp(int n) {
    const int base = (blockIdx.x * 256 + threadIdx.x) * ITEMS;
    if (base >= n) return;
    const int m = (n - base < ITEMS) ? (n - base) : ITEMS;

    float xk[ITEMS];
    #pragma unroll
    for (int t = 0; t < ITEMS; t++)
        xk[t] = (t < m) ? __ldg(&g_xs[base + t]) : 0.0f;

    float A[ITEMS], B[ITEMS];

    // ---------- side A: q = xk + delta, bracket >= base ----------
    {
        float q0 = xk[0] + DELTA_F;
        int w_lo = base + SEED_OFF - SEED_HALF; if (w_lo < base) w_lo = base;
        int w_hi = base + SEED_OFF + SEED_HALF; if (w_hi > n) w_hi = n;
        int lo;
        bool ok_lo = (w_lo == base) || (w_lo < n && __ldg(&g_xs[w_lo]) <= q0);
        bool ok_hi = (w_hi == n)   || (__ldg(&g_xs[w_hi]) > q0);
        if (ok_lo && ok_hi && w_lo <= w_hi) {
            lo = bsearch_gt(q0, w_lo, w_hi);
        } else {                                   // general-input fallback
            int off = 8192;
            while (base + off < n && __ldg(&g_xs[base + off]) <= q0) off <<= 1;
            int hi = (base + off < n) ? (base + off) : n;
            lo = bsearch_gt(q0, base, hi);
        }
        int jA = lo - 1;
        #pragma unroll
        for (int t = 0; t < ITEMS; t++) {
            if (t >= m) break;
            float q = xk[t] + DELTA_F;
            while (jA + 1 < n && __ldg(&g_xs[jA + 1]) <= q) jA++;
            if (jA >= n - 1) {
                A[t] = __ldg(&g_ys[n - 1]);
            } else {
                float x0 = __ldg(&g_xs[jA]), x1 = __ldg(&g_xs[jA + 1]);
                float y0 = __ldg(&g_ys[jA]), y1 = __ldg(&g_ys[jA + 1]);
                A[t] = y0 + (q - x0) * (y1 - y0) / (x1 - x0);
            }
        }
    }

    // ---------- side B: q = xk - delta, bracket <= base-1 ----------
    {
        float q0 = xk[0] - DELTA_F;
        int w_lo = base - SEED_OFF - SEED_HALF; if (w_lo < 0) w_lo = 0;
        int w_hi = base - SEED_OFF + SEED_HALF; if (w_hi > base) w_hi = base; if (w_hi < 0) w_hi = 0;
        int lo;
        bool ok_lo = (w_lo == 0)    || (__ldg(&g_xs[w_lo]) <= q0);
        bool ok_hi = (w_hi == base) || (__ldg(&g_xs[w_hi]) > q0);
        if (ok_lo && ok_hi && w_lo <= w_hi) {
            lo = bsearch_gt(q0, w_lo, w_hi);
        } else {                                   // general-input fallback
            int off = 8192;
            while (base - off >= 0 && __ldg(&g_xs[base - off]) > q0) off <<= 1;
            int l2 = (base - off > 0) ? (base - off) : 0;
            lo = bsearch_gt(q0, l2, base);
        }
        int jB = lo - 1;
        #pragma unroll
        for (int t = 0; t < ITEMS; t++) {
            if (t >= m) break;
            float q = xk[t] - DELTA_F;
            while (jB + 1 < n && __ldg(&g_xs[jB + 1]) <= q) jB++;
            if (jB < 0) {
                B[t] = __ldg(&g_ys[0]);
            } else if (jB >= n - 1) {
                B[t] = __ldg(&g_ys[n - 1]);
            } else {
                float x0 = __ldg(&g_xs[jB]), x1 = __ldg(&g_xs[jB + 1]);
                float y0 = __ldg(&g_ys[jB]), y1 = __ldg(&g_ys[jB + 1]);
                B[t] = y0 + (q - x0) * (y1 - y0) / (x1 - x0);
            }
        }
    }

    // scatter (A,B) as half2 to original positions; NORMAL stores so the
    // 64 MB AB array stays L2-resident (whole-line accumulation on-chip)
    #pragma unroll
    for (int t = 0; t < ITEMS; t++) {
        if (t >= m) break;
        unsigned int o = __ldcs(&g_idx[base + t]);   // idx is single-use: evict-first
        g_AB[o] = __floats2half2_rn(A[t], B[t]);
    }
}

// gap_i = relu(A_i - B_{i+1}); AB is L2-resident half2. 4 gaps per thread.
__global__ __launch_bounds__(256) void k_gap(int n) {
    float acc = 0.0f;
    int stride = gridDim.x * blockDim.x;
    for (int t = blockIdx.x * blockDim.x + threadIdx.x; 4 * t < n - 1; t += stride) {
        int i = 4 * t;
        uint4 u = *(const uint4*)&g_AB[i];           // AB[i..i+3]
        __half2 h0 = *(__half2*)&u.x;
        __half2 h1 = *(__half2*)&u.y;
        __half2 h2 = *(__half2*)&u.z;
        __half2 h3 = *(__half2*)&u.w;
        acc += fmaxf(__low2float(h0) - __high2float(h1), 0.0f);
        acc += fmaxf(__low2float(h1) - __high2float(h2), 0.0f);
        acc += fmaxf(__low2float(h2) - __high2float(h3), 0.0f);
        if (i + 4 < n) {
            __half2 h4 = g_AB[i + 4];
            acc += fmaxf(__low2float(h3) - __high2float(h4), 0.0f);
        }
    }
    typedef cub::BlockReduce<float, 256> BR;
    __shared__ typename BR::TempStorage ts;
    float s = BR(ts).Sum(acc);
    if (threadIdx.x == 0) atomicAdd(&g_accum, (double)s);
}

__global__ void k_final(float* __restrict__ out) {
    out[0] = (float)((double)ALPHA_F * g_accum);
}

extern "C" void kernel_launch(void* const* d_in, const int* in_sizes, int n_in,
                              void* d_out, int out_size) {
    const float* indices = (const float*)d_in[0];
    const float* array   = (const float*)d_in[1];
    int n = in_sizes[0];

    float* p_clamped = nullptr;
    float* p_xs = nullptr;
    unsigned int* p_idx_in = nullptr;
    unsigned int* p_idx = nullptr;
    void*  p_temp = nullptr;
    cudaGetSymbolAddress((void**)&p_clamped, g_clamped);
    cudaGetSymbolAddress((void**)&p_xs, g_xs);
    cudaGetSymbolAddress((void**)&p_idx_in, g_idx_in);
    cudaGetSymbolAddress((void**)&p_idx, g_idx);
    cudaGetSymbolAddress(&p_temp, g_temp);

    const int threads = 256;
    int n4 = n / 4;
    int b4 = (n4 + threads - 1) / threads;

    // 1) clamp + iota (vectorized) + zero accumulator
    k_init<<<b4, threads>>>((const float4*)indices, n4);

    // 2) full 32-bit stable sort (exact order is load-bearing; R8 proved it)
    size_t temp_bytes = sizeof(g_temp);
    cub::DeviceRadixSort::SortPairs(p_temp, temp_bytes,
                                    p_clamped, p_xs,
                                    p_idx_in, p_idx,
                                    n, 0, 32);

    // 3) gather y-values into sorted order (vectorized idx read)
    k_gather<<<b4, threads>>>(array, n4);

    // 4) sorted-domain merge-interpolation (seeded search), L2-resident AB scatter
    int chunk_blocks = (n + threads * ITEMS - 1) / (threads * ITEMS);
    k_interp<<<chunk_blocks, threads>>>(n);

    // 5) gap + reduction (AB reads hit L2)
    k_gap<<<592, threads>>>(n);

    // 6) scale + write scalar output
    k_final<<<1, 1>>>((float*)d_out);
}

// round 14
// speedup vs baseline: 1.5140x; 1.5140x over previous
#include <cuda_runtime.h>
#include <cuda_bf16.h>
#include <cuda_fp16.h>
#include <cub/cub.cuh>
#include <cstdint>

#define ALPHA_F 10.0f
#define DELTA_F 0.0005f
#define SEED_OFF 8389          // delta * N for N=2^24 (seed only; exactness checked per query)
#define CHUNK 2048             // sorted positions per block
#define MARGIN 512             // window slack each side (5.5 sigma of bracket deviation)
#define WSZ (CHUNK + 2 * MARGIN)   // 3072 floats = 12KB per window array

// ---- scratch (device globals: allocation-free rule) ----
__device__ float        g_clamped[16777216];
__device__ float        g_xs[16777216];
__device__ unsigned int g_idx_in[16777216];
__device__ unsigned int g_idx[16777216];
__device__ float        g_ys[16777216];
__device__ __half2      g_AB[16777216];                 // 64 MB, streamed (evict-first)
__device__ unsigned char g_temp[200u * 1024u * 1024u];
__device__ double       g_accum;

__global__ __launch_bounds__(256) void k_init(const float4* __restrict__ in4, int n4) {
    int t = blockIdx.x * blockDim.x + threadIdx.x;
    if (t == 0) g_accum = 0.0;
    if (t >= n4) return;
    float4 v = __ldg(&in4[t]);
    float4 c;
    c.x = fminf(fmaxf(v.x, 0.0f), 1.0f);
    c.y = fminf(fmaxf(v.y, 0.0f), 1.0f);
    c.z = fminf(fmaxf(v.z, 0.0f), 1.0f);
    c.w = fminf(fmaxf(v.w, 0.0f), 1.0f);
    ((float4*)g_clamped)[t] = c;
    unsigned int i0 = (unsigned int)t * 4u;
    ((uint4*)g_idx_in)[t] = make_uint4(i0, i0 + 1, i0 + 2, i0 + 3);
}

__global__ __launch_bounds__(256) void k_gather(const float* __restrict__ array, int n4) {
    int t = blockIdx.x * blockDim.x + threadIdx.x;
    if (t >= n4) return;
    uint4 id = __ldg(&((const uint4*)g_idx)[t]);
    float4 y;
    y.x = __ldg(&array[id.x]);
    y.y = __ldg(&array[id.y]);
    y.z = __ldg(&array[id.z]);
    y.w = __ldg(&array[id.w]);
    ((float4*)g_ys)[t] = y;
}

// exact global fallback: full binary search over [0, n)  (rare)
__device__ __noinline__ float eval_global(float q, int n) {
    int lo = 0, hi = n;                    // first index with xs > q
    while (lo < hi) {
        int mid = (lo + hi) >> 1;
        if (__ldg(&g_xs[mid]) <= q) lo = mid + 1; else hi = mid;
    }
    int j = lo - 1;
    if (j < 0)      return __ldg(&g_ys[0]);
    if (j >= n - 1) return __ldg(&g_ys[n - 1]);
    float x0 = __ldg(&g_xs[j]), x1 = __ldg(&g_xs[j + 1]);
    float y0 = __ldg(&g_ys[j]), y1 = __ldg(&g_ys[j + 1]);
    return y0 + (q - x0) * (y1 - y0) / (x1 - x0);
}

// Evaluate f(q) from a staged smem window sx/sy = xs/ys[s0 .. s0+w).
// p = first window slot with x > q. Interior p proves the global bracket;
// boundary p resolves exactly iff the window touches the array end, else
// falls back to the exact global search. np.interp fill semantics preserved.
__device__ __forceinline__ float eval_win(float q, const float* __restrict__ sx,
                                          const float* __restrict__ sy,
                                          int s0, int w, int n) {
    int lo = 0, hi = w;
    while (lo < hi) {
        int mid = (lo + hi) >> 1;
        if (sx[mid] <= q) lo = mid + 1; else hi = mid;
    }
    if (lo == 0) {
        if (s0 == 0) return sy[0];                 // q < xs[0] -> left fill
        return eval_global(q, n);
    }
    if (lo == w) {
        if (s0 + w == n) return sy[w - 1];         // q >= xs[n-1] -> right fill
        return eval_global(q, n);
    }
    float x0 = sx[lo - 1], x1 = sx[lo];
    float y0 = sy[lo - 1], y1 = sy[lo];
    return y0 + (q - x0) * (y1 - y0) / (x1 - x0);  // x1 > q >= x0
}

__global__ __launch_bounds__(256) void k_interp(int n) {
    __shared__ float sxa[WSZ], sya[WSZ], sxb[WSZ], syb[WSZ];

    const int K = blockIdx.x * CHUNK;
    if (K >= n) return;

    // window placement (clamped; exactness is re-verified per query)
    int sa = K + SEED_OFF - MARGIN;
    if (sa > n - WSZ) sa = n - WSZ;
    if (sa < 0) sa = 0;
    sa &= ~3;
    int wa = min(WSZ, n - sa);

    int sb = K - SEED_OFF - MARGIN;
    if (sb > n - WSZ) sb = n - WSZ;
    if (sb < 0) sb = 0;
    sb &= ~3;
    int wb = min(WSZ, n - sb);

    // cooperative staging (coalesced float4; tail overrun stays inside symbols)
    {
        int wa4 = (wa + 3) >> 2, wb4 = (wb + 3) >> 2;
        const float4* xa4 = (const float4*)(g_xs + sa);
        const float4* ya4 = (const float4*)(g_ys + sa);
        const float4* xb4 = (const float4*)(g_xs + sb);
        const float4* yb4 = (const float4*)(g_ys + sb);
        for (int i = threadIdx.x; i < wa4; i += 256) {
            ((float4*)sxa)[i] = __ldg(&xa4[i]);
            ((float4*)sya)[i] = __ldg(&ya4[i]);
        }
        for (int i = threadIdx.x; i < wb4; i += 256) {
            ((float4*)sxb)[i] = __ldg(&xb4[i]);
            ((float4*)syb)[i] = __ldg(&yb4[i]);
        }
    }
    __syncthreads();

    // each thread owns 8 consecutive positions of this block's chunk
    const int base = K + threadIdx.x * 8;
    if (base >= n) return;
    const int m = (n - base < 8) ? (n - base) : 8;

    float xk[8];
    if (m == 8) {
        float4 a = __ldg((const float4*)&g_xs[base]);
        float4 b = __ldg((const float4*)&g_xs[base + 4]);
        xk[0]=a.x; xk[1]=a.y; xk[2]=a.z; xk[3]=a.w;
        xk[4]=b.x; xk[5]=b.y; xk[6]=b.z; xk[7]=b.w;
    } else {
        for (int t = 0; t < 8; t++) xk[t] = (t < m) ? __ldg(&g_xs[base + t]) : 0.0f;
    }

    unsigned int oidx[8];
    if (m == 8) {
        uint4 a = __ldcs((const uint4*)&g_idx[base]);
        uint4 b = __ldcs((const uint4*)&g_idx[base + 4]);
        oidx[0]=a.x; oidx[1]=a.y; oidx[2]=a.z; oidx[3]=a.w;
        oidx[4]=b.x; oidx[5]=b.y; oidx[6]=b.z; oidx[7]=b.w;
    } else {
        for (int t = 0; t < m; t++) oidx[t] = __ldcs(&g_idx[base + t]);
    }

    #pragma unroll
    for (int t = 0; t < 8; t++) {
        if (t >= m) break;
        float A = eval_win(xk[t] + DELTA_F, sxa, sya, sa, wa, n);
        float B = eval_win(xk[t] - DELTA_F, sxb, syb, sb, wb, n);
        __stcs(&g_AB[oidx[t]], __floats2half2_rn(A, B));
    }
}

// gap_i = relu(A_i - B_{i+1}); streamed half2 reads, 4 gaps per thread
__global__ __launch_bounds__(256) void k_gap(int n) {
    float acc = 0.0f;
    int stride = gridDim.x * blockDim.x;
    for (int t = blockIdx.x * blockDim.x + threadIdx.x; 4 * t < n - 1; t += stride) {
        int i = 4 * t;
        uint4 u = __ldcs((const uint4*)&g_AB[i]);     // AB[i..i+3]
        __half2 h0 = *(__half2*)&u.x;
        __half2 h1 = *(__half2*)&u.y;
        __half2 h2 = *(__half2*)&u.z;
        __half2 h3 = *(__half2*)&u.w;
        acc += fmaxf(__low2float(h0) - __high2float(h1), 0.0f);
        acc += fmaxf(__low2float(h1) - __high2float(h2), 0.0f);
        acc += fmaxf(__low2float(h2) - __high2float(h3), 0.0f);
        if (i + 4 < n) {
            __half2 h4 = g_AB[i + 4];
            acc += fmaxf(__low2float(h3) - __high2float(h4), 0.0f);
        }
    }
    typedef cub::BlockReduce<float, 256> BR;
    __shared__ typename BR::TempStorage ts;
    float s = BR(ts).Sum(acc);
    if (threadIdx.x == 0) atomicAdd(&g_accum, (double)s);
}

__global__ void k_final(float* __restrict__ out) {
    out[0] = (float)((double)ALPHA_F * g_accum);
}

extern "C" void kernel_launch(void* const* d_in, const int* in_sizes, int n_in,
                              void* d_out, int out_size) {
    const float* indices = (const float*)d_in[0];
    const float* array   = (const float*)d_in[1];
    int n = in_sizes[0];

    float* p_clamped = nullptr;
    float* p_xs = nullptr;
    unsigned int* p_idx_in = nullptr;
    unsigned int* p_idx = nullptr;
    void*  p_temp = nullptr;
    cudaGetSymbolAddress((void**)&p_clamped, g_clamped);
    cudaGetSymbolAddress((void**)&p_xs, g_xs);
    cudaGetSymbolAddress((void**)&p_idx_in, g_idx_in);
    cudaGetSymbolAddress((void**)&p_idx, g_idx);
    cudaGetSymbolAddress(&p_temp, g_temp);

    const int threads = 256;
    int n4 = n / 4;
    int b4 = (n4 + threads - 1) / threads;

    // 1) clamp + iota (vectorized) + zero accumulator
    k_init<<<b4, threads>>>((const float4*)indices, n4);

    // 2) full 32-bit stable sort (exact order is load-bearing; R8 proved it)
    size_t temp_bytes = sizeof(g_temp);
    cub::DeviceRadixSort::SortPairs(p_temp, temp_bytes,
                                    p_clamped, p_xs,
                                    p_idx_in, p_idx,
                                    n, 0, 32);

    // 3) gather y-values into sorted order
    k_gather<<<b4, threads>>>(array, n4);

    // 4) block-windowed smem interpolation, streaming half2 AB scatter
    int iblocks = (n + CHUNK - 1) / CHUNK;
    k_interp<<<iblocks, threads>>>(n);

    // 5) gap + reduction
    k_gap<<<592, threads>>>(n);

    // 6) scale + write scalar output
    k_final<<<1, 1>>>((float*)d_out);
}